// round 15
// baseline (speedup 1.0000x reference)
#include <cuda_runtime.h>

#define T_TRIG 48
#define S_SPAN 128
#define NNODE  (T_TRIG * S_SPAN)     // 6144
#define DIM    128
#define NHEADS 4
#define HDIM   32

typedef unsigned long long ull;
typedef unsigned int uint;

__device__ float g_h   [NNODE * DIM];
__device__ float g_A   [NNODE * NHEADS];
__device__ float g_B   [NNODE * NHEADS];
__device__ float g_EA  [NNODE * NHEADS];
__device__ float g_EA5 [NNODE * NHEADS];
__device__ float g_EB  [NNODE * NHEADS];
__device__ float g_EB5 [NNODE * NHEADS];
__device__ float g_srow[NNODE * NHEADS];
__device__ float g_scol[NNODE * NHEADS];
__device__ float g_tmp [NNODE * DIM];     // row partial (unnormalized)
__device__ float g_tmp2[NNODE * DIM];     // col partial (unnormalized)
__device__ float4 g_Wf [2 * 16 * 16 * 32];

// ---- packed f32x2 helpers ---------------------------------------------------
__device__ __forceinline__ ull pk2(float x, float y) {
    ull r; asm("mov.b64 %0, {%1, %2};" : "=l"(r) : "f"(x), "f"(y)); return r;
}
__device__ __forceinline__ float2 upk2(ull v) {
    float2 r; asm("mov.b64 {%0, %1}, %2;" : "=f"(r.x), "=f"(r.y) : "l"(v)); return r;
}
__device__ __forceinline__ void fma2(ull& d, ull a, ull b) {
    asm("fma.rn.f32x2 %0, %1, %2, %0;" : "+l"(d) : "l"(a), "l"(b));
}

// ---- tf32 helpers -------------------------------------------------------------
__device__ __forceinline__ uint cvt_tf32(float f) {
    uint r; asm("cvt.rna.tf32.f32 %0, %1;" : "=r"(r) : "f"(f)); return r;
}
__device__ __forceinline__ void mma_tf32(float& d0, float& d1, float& d2, float& d3,
                                         uint a0, uint a1, uint a2, uint a3,
                                         uint b0, uint b1) {
    asm("mma.sync.aligned.m16n8k8.row.col.f32.tf32.tf32.f32 "
        "{%0,%1,%2,%3}, {%4,%5,%6,%7}, {%8,%9}, {%0,%1,%2,%3};"
        : "+f"(d0), "+f"(d1), "+f"(d2), "+f"(d3)
        : "r"(a0), "r"(a1), "r"(a2), "r"(a3), "r"(b0), "r"(b1));
}

__device__ __forceinline__ float elu1(float v) {
    return v > 0.f ? v : (__expf(v) - 1.f);
}

// ---------------------------------------------------------------------------
// K0: pack W1/W2 into fragment order with tf32 hi/lo split. (R10, unchanged)
// ---------------------------------------------------------------------------
__global__ void __launch_bounds__(256)
k_prep(const float* __restrict__ W1, const float* __restrict__ W2)
{
    const int gid   = blockIdx.x * 256 + threadIdx.x;
    const int layer = gid >> 13;
    const int e     = gid & 8191;
    const int lane  = e & 31;
    const int nt    = (e >> 5) & 15;
    const int ks    = e >> 9;

    const float* W = layer ? W2 : W1;
    const int k0 = ks * 8 + (lane & 3);
    const int n  = nt * 8 + (lane >> 2);

    const float b0 = W[k0 * 128 + n];
    const float b1 = W[(k0 + 4) * 128 + n];
    const uint b0h = cvt_tf32(b0);
    const uint b1h = cvt_tf32(b1);
    const uint b0l = cvt_tf32(b0 - __uint_as_float(b0h));
    const uint b1l = cvt_tf32(b1 - __uint_as_float(b1h));

    g_Wf[layer * 8192 + e] = make_float4(__uint_as_float(b0h), __uint_as_float(b1h),
                                         __uint_as_float(b0l), __uint_as_float(b1l));
}

// ---------------------------------------------------------------------------
// K1: h = x @ W via tensor cores (3xTF32) + attention dots + 4 exps.
// fused=0: x from xin. fused=1: x = ELU((g_tmp+g_tmp2)*rd + biasIn) computed
// inline during staging (layer-1 combine fused into layer-2 GEMM).
// ---------------------------------------------------------------------------
__global__ void __launch_bounds__(128)
k_gemm_attn(const float* __restrict__ xin,
            const float4* __restrict__ Wf,
            const float* __restrict__ att_src,
            const float* __restrict__ att_dst,
            const float* __restrict__ biasIn,
            const int fused)
{
    __shared__ __align__(16) float xs[16 * 132];

    const int tid  = threadIdx.x;
    const int row0 = blockIdx.x * 16;

    if (!fused) {
#pragma unroll
        for (int i = 0; i < 4; i++) {
            const int idx = tid + 128 * i;
            const int row = idx >> 5, c4 = idx & 31;
            *(float4*)&xs[row * 132 + c4 * 4] =
                ((const float4*)(xin + row0 * 128))[idx];
        }
    } else {
#pragma unroll
        for (int i = 0; i < 4; i++) {
            const int idx = tid + 128 * i;
            const int row = idx >> 5, c4 = idx & 31;
            const int n = row0 + row;
            const int h = c4 >> 3;
            const float rd = 1.f / (g_srow[n * 4 + h] + g_scol[n * 4 + h]);
            const float4 t1 = ((const float4*)g_tmp )[n * 32 + c4];
            const float4 t2 = ((const float4*)g_tmp2)[n * 32 + c4];
            const float4 bv = ((const float4*)biasIn)[c4];
            float4 o;
            o.x = elu1((t1.x + t2.x) * rd + bv.x);
            o.y = elu1((t1.y + t2.y) * rd + bv.y);
            o.z = elu1((t1.z + t2.z) * rd + bv.z);
            o.w = elu1((t1.w + t2.w) * rd + bv.w);
            *(float4*)&xs[row * 132 + c4 * 4] = o;
        }
    }
    __syncthreads();

    const int warp = tid >> 5;
    const int lane = tid & 31;
    const int gid  = lane >> 2;
    const int tig  = lane & 3;

    float d[4][4];
#pragma unroll
    for (int nt = 0; nt < 4; nt++)
#pragma unroll
        for (int i = 0; i < 4; i++) d[nt][i] = 0.f;

#pragma unroll 4
    for (int ks = 0; ks < 16; ks++) {
        const float a0f = xs[gid * 132 + ks * 8 + tig];
        const float a1f = xs[(gid + 8) * 132 + ks * 8 + tig];
        const float a2f = xs[gid * 132 + ks * 8 + tig + 4];
        const float a3f = xs[(gid + 8) * 132 + ks * 8 + tig + 4];
        const uint ah0 = cvt_tf32(a0f), ah1 = cvt_tf32(a1f);
        const uint ah2 = cvt_tf32(a2f), ah3 = cvt_tf32(a3f);
        const uint al0 = cvt_tf32(a0f - __uint_as_float(ah0));
        const uint al1 = cvt_tf32(a1f - __uint_as_float(ah1));
        const uint al2 = cvt_tf32(a2f - __uint_as_float(ah2));
        const uint al3 = cvt_tf32(a3f - __uint_as_float(ah3));

#pragma unroll
        for (int nt = 0; nt < 4; nt++) {
            const float4 bf = __ldg(&Wf[(ks * 16 + warp * 4 + nt) * 32 + lane]);
            const uint bh0 = __float_as_uint(bf.x);
            const uint bh1 = __float_as_uint(bf.y);
            const uint bl0 = __float_as_uint(bf.z);
            const uint bl1 = __float_as_uint(bf.w);
            mma_tf32(d[nt][0], d[nt][1], d[nt][2], d[nt][3],
                     ah0, ah1, ah2, ah3, bh0, bh1);
            mma_tf32(d[nt][0], d[nt][1], d[nt][2], d[nt][3],
                     ah0, ah1, ah2, ah3, bl0, bl1);
            mma_tf32(d[nt][0], d[nt][1], d[nt][2], d[nt][3],
                     al0, al1, al2, al3, bh0, bh1);
        }
    }

    float psr0 = 0.f, psr8 = 0.f, pdr0 = 0.f, pdr8 = 0.f;
#pragma unroll
    for (int nt = 0; nt < 4; nt++) {
        const int col = warp * 32 + nt * 8 + 2 * tig;
        *(float2*)&g_h[(row0 + gid) * 128 + col]     = make_float2(d[nt][0], d[nt][1]);
        *(float2*)&g_h[(row0 + gid + 8) * 128 + col] = make_float2(d[nt][2], d[nt][3]);

        const float2 as = *(const float2*)&att_src[col];
        const float2 ad = *(const float2*)&att_dst[col];
        psr0 += d[nt][0] * as.x + d[nt][1] * as.y;
        psr8 += d[nt][2] * as.x + d[nt][3] * as.y;
        pdr0 += d[nt][0] * ad.x + d[nt][1] * ad.y;
        pdr8 += d[nt][2] * ad.x + d[nt][3] * ad.y;
    }
#pragma unroll
    for (int o = 1; o < 4; o <<= 1) {
        psr0 += __shfl_xor_sync(0xffffffffu, psr0, o);
        psr8 += __shfl_xor_sync(0xffffffffu, psr8, o);
        pdr0 += __shfl_xor_sync(0xffffffffu, pdr0, o);
        pdr8 += __shfl_xor_sync(0xffffffffu, pdr8, o);
    }
    if (tig == 0) {
        const int n0 = row0 + gid;
        const int n8 = row0 + gid + 8;
        int i4 = n0 * 4 + warp;
        g_A[i4] = psr0;  g_B[i4] = pdr0;
        g_EA[i4]  = __expf(psr0);        g_EB[i4]  = __expf(pdr0);
        g_EA5[i4] = __expf(0.2f * psr0); g_EB5[i4] = __expf(0.2f * pdr0);
        i4 = n8 * 4 + warp;
        g_A[i4] = psr8;  g_B[i4] = pdr8;
        g_EA[i4]  = __expf(psr8);        g_EB[i4]  = __expf(pdr8);
        g_EA5[i4] = __expf(0.2f * psr8); g_EB5[i4] = __expf(0.2f * pdr8);
    }
}

// ---------------------------------------------------------------------------
// K2: FUSED aggregation. grid = 640, 256 threads.
//  blocks [0,384): row aggregation (r, head, c-half) -> g_tmp, g_srow
//  blocks [384,640): col partial (c, r-half) -> g_tmp2, g_scol (self excluded)
// The two families are independent (both read only gemm outputs), so they
// fill the chip together instead of running as two underfilled kernels.
// ---------------------------------------------------------------------------
__global__ void __launch_bounds__(256)
k_agg_fused()
{
    __shared__ __align__(16) float S[8192];   // 32 KB carved per path
    const int bid = blockIdx.x;
    const int tid = threadIdx.x;

    if (bid < 384) {
        // ---------------- row path (R11 row_agg) ----------------
        const int r  = bid >> 3;
        const int hh = (bid >> 1) & 3;
        const int ch = bid & 1;

        float* Hs   = S;              // 128*36 = 4608
        float* ws   = S + 4608;       // 32*68  = 2176
        float* As   = S + 6784;       // 128
        float* EAs  = S + 6912;       // 128
        float* EA5s = S + 7040;       // 128
        float* Bs   = S + 7168;       // 64
        float* EBs  = S + 7232;       // 64
        float* EB5s = S + 7296;       // 64
        float* Ssum = S + 7360;       // 4*64 = 256

#pragma unroll
        for (int i = tid; i < 1024; i += 256) {
            const int cp = i >> 3, v = i & 7;
            *(float4*)&Hs[cp * 36 + v * 4] =
                *(const float4*)&g_h[(r * 128 + cp) * 128 + hh * 32 + v * 4];
        }
        if (tid < 128) {
            const int idx = (r * 128 + tid) * 4 + hh;
            As  [tid] = g_A  [idx];
            EAs [tid] = g_EA [idx];
            EA5s[tid] = g_EA5[idx];
        } else if (tid < 192) {
            const int idx = (r * 128 + ch * 64 + (tid - 128)) * 4 + hh;
            Bs  [tid - 128] = g_B  [idx];
            EBs [tid - 128] = g_EB [idx];
            EB5s[tid - 128] = g_EB5[idx];
        }
        __syncthreads();

        const int d  = tid & 63;
        const int jh = tid >> 6;
        const float Bv   = Bs[d];
        const float EBv  = EBs[d];
        const float EB5v = EB5s[d];
        float srun = 0.f;

        const int dg = tid >> 3;
        const int qg = tid & 7;

        ull acc2[2][2];
        acc2[0][0] = acc2[0][1] = acc2[1][0] = acc2[1][1] = 0ull;

        for (int cc = 0; cc < 4; cc++) {
#pragma unroll
            for (int jj = 0; jj < 8; jj++) {
                const int j  = jh * 8 + jj;
                const int jx = cc * 32 + j;
                const float xv = As[jx] + Bv;
                const float w = xv > 0.f ? EAs[jx] * EBv : EA5s[jx] * EB5v;
                ws[j * 68 + d] = w;
                srun += w;
            }
            __syncthreads();

#pragma unroll
            for (int j = 0; j < 32; j++) {
                const float2 wv = *(const float2*)&ws[j * 68 + dg * 2];
                const ulonglong2 hv = *(const ulonglong2*)&Hs[(cc * 32 + j) * 36 + qg * 4];
                ull ww;
                ww = pk2(wv.x, wv.x); fma2(acc2[0][0], ww, hv.x); fma2(acc2[0][1], ww, hv.y);
                ww = pk2(wv.y, wv.y); fma2(acc2[1][0], ww, hv.x); fma2(acc2[1][1], ww, hv.y);
            }
            __syncthreads();
        }

#pragma unroll
        for (int a = 0; a < 2; a++) {
            const int dst = ch * 64 + dg * 2 + a;
            const float2 lo = upk2(acc2[a][0]);
            const float2 hi = upk2(acc2[a][1]);
            *(float4*)&g_tmp[(r * 128 + dst) * 128 + hh * 32 + qg * 4] =
                make_float4(lo.x, lo.y, hi.x, hi.y);
        }

        Ssum[jh * 64 + d] = srun;
        __syncthreads();
        if (tid < 64)
            g_srow[(r * 128 + ch * 64 + tid) * 4 + hh] =
                Ssum[tid] + Ssum[64 + tid] + Ssum[128 + tid] + Ssum[192 + tid];
    } else {
        // ---------------- col path (inline weights, self excluded) ----------
        const int b2 = bid - 384;
        const int c  = b2 >> 1;
        const int rh = b2 & 1;

        float* Hc   = S;              // 48*144 = 6912
        float* Ac   = S + 6912;       // 192
        float* EAc  = S + 7104;       // 192
        float* EA5c = S + 7296;       // 192
        float* Bc   = S + 7488;       // 96
        float* EBc  = S + 7584;       // 96
        float* EB5c = S + 7680;       // 96

#pragma unroll
        for (int i = tid; i < 1536; i += 256) {
            const int t = i >> 5, v = i & 31;
            *(float4*)&Hc[t * 144 + (v >> 3) * 36 + (v & 7) * 4] =
                *(const float4*)&g_h[(t * 128 + c) * 128 + v * 4];
        }
        if (tid < 192) {
            const int t = tid >> 2, h = tid & 3;
            const int idx = (t * 128 + c) * 4 + h;
            Ac  [tid] = g_A  [idx];
            EAc [tid] = g_EA [idx];
            EA5c[tid] = g_EA5[idx];
        } else {
            const int k = tid - 192;   // 0..63 -> covers 96 via two loads
            if (k < 96) {
                const int rg = rh * 24 + (k >> 2), h = k & 3;
                const int idx = (rg * 128 + c) * 4 + h;
                Bc  [k] = g_B  [idx];
                EBc [k] = g_EB [idx];
                EB5c[k] = g_EB5[idx];
            }
        }
        // remaining 32 entries of Bc staged by first 32 threads (after their load)
        if (tid < 32) {
            const int k = 64 + tid;
            const int rg = rh * 24 + (k >> 2), h = k & 3;
            const int idx = (rg * 128 + c) * 4 + h;
            Bc  [k] = g_B  [idx];
            EBc [k] = g_EB [idx];
            EB5c[k] = g_EB5[idx];
        }
        __syncthreads();

        if (tid < 192) {
            const int rl   = tid >> 3;
            const int head = (tid >> 1) & 3;
            const int q    = tid & 1;
            const int k    = rl * 4 + head;
            const int rglob = rh * 24 + rl;
            const float Bv   = Bc[k];
            const float EBv  = EBc[k];
            const float EB5v = EB5c[k];

            ull acc[8];
#pragma unroll
            for (int a = 0; a < 8; a++) acc[a] = 0ull;
            float scrun = 0.f;

#pragma unroll 4
            for (int t = 0; t < 48; t++) {
                const int sx = t * 4 + head;
                const float xv = Ac[sx] + Bv;
                float w = xv > 0.f ? EAc[sx] * EBv : EA5c[sx] * EB5v;
                if (t == rglob) w = 0.f;
                scrun += w;
                const ull ww = pk2(w, w);
                const float* hp = &Hc[t * 144 + head * 36 + q * 16];
                const ulonglong2 h0 = *(const ulonglong2*)&hp[0];
                const ulonglong2 h1 = *(const ulonglong2*)&hp[4];
                const ulonglong2 h2 = *(const ulonglong2*)&hp[8];
                const ulonglong2 h3 = *(const ulonglong2*)&hp[12];
                fma2(acc[0], ww, h0.x); fma2(acc[1], ww, h0.y);
                fma2(acc[2], ww, h1.x); fma2(acc[3], ww, h1.y);
                fma2(acc[4], ww, h2.x); fma2(acc[5], ww, h2.y);
                fma2(acc[6], ww, h3.x); fma2(acc[7], ww, h3.y);
            }

            const int base = (rglob * 128 + c) * 128 + head * 32 + q * 16;
#pragma unroll
            for (int a = 0; a < 4; a++) {
                const float2 lo = upk2(acc[a * 2]);
                const float2 hi = upk2(acc[a * 2 + 1]);
                *(float4*)&g_tmp2[base + a * 4] =
                    make_float4(lo.x, lo.y, hi.x, hi.y);
            }
            if (q == 0)
                g_scol[(rglob * 128 + c) * 4 + head] = scrun;
        }
    }
}

// ---------------------------------------------------------------------------
// K3: final combine (layer 2 only): out = ELU((tmp+tmp2)*rd + bias).
// grid = 768, 256 threads; thread = one float4 of one node.
// ---------------------------------------------------------------------------
__global__ void __launch_bounds__(256)
k_combine(const float* __restrict__ bias, float* __restrict__ out)
{
    const int node = blockIdx.x * 8 + (threadIdx.x >> 5);
    const int v    = threadIdx.x & 31;
    const int h    = v >> 3;

    const float rd = 1.f / (g_srow[node * 4 + h] + g_scol[node * 4 + h]);
    const float4 t1 = ((const float4*)g_tmp )[node * 32 + v];
    const float4 t2 = ((const float4*)g_tmp2)[node * 32 + v];
    const float4 bv = ((const float4*)bias)[v];
    float4 o;
    o.x = elu1((t1.x + t2.x) * rd + bv.x);
    o.y = elu1((t1.y + t2.y) * rd + bv.y);
    o.z = elu1((t1.z + t2.z) * rd + bv.z);
    o.w = elu1((t1.w + t2.w) * rd + bv.w);
    ((float4*)out)[node * 32 + v] = o;
}

// ---------------------------------------------------------------------------
extern "C" void kernel_launch(void* const* d_in, const int* in_sizes, int n_in,
                              void* d_out, int out_size)
{
    const float* x0  = (const float*)d_in[0];
    const float* W1  = (const float*)d_in[1];
    const float* as1 = (const float*)d_in[2];
    const float* ad1 = (const float*)d_in[3];
    const float* b1  = (const float*)d_in[4];
    const float* W2  = (const float*)d_in[5];
    const float* as2 = (const float*)d_in[6];
    const float* ad2 = (const float*)d_in[7];
    const float* b2  = (const float*)d_in[8];

    float4* Wf = nullptr;
    cudaGetSymbolAddress((void**)&Wf, g_Wf);

    k_prep<<<64, 256>>>(W1, W2);
    // layer 1
    k_gemm_attn<<<NNODE / 16, 128>>>(x0, Wf, as1, ad1, nullptr, 0);
    k_agg_fused<<<640, 256>>>();
    // layer 2 (combine of layer 1 fused into GEMM staging)
    k_gemm_attn<<<NNODE / 16, 128>>>(nullptr, Wf + 8192, as2, ad2, b1, 1);
    k_agg_fused<<<640, 256>>>();
    k_combine<<<768, 256>>>(b2, (float*)d_out);
}

// round 16
// speedup vs baseline: 1.2321x; 1.2321x over previous
#include <cuda_runtime.h>

#define T_TRIG 48
#define S_SPAN 128
#define NNODE  (T_TRIG * S_SPAN)     // 6144
#define DIM    128
#define NHEADS 4
#define HDIM   32

typedef unsigned long long ull;
typedef unsigned int uint;

__device__ float g_h   [NNODE * DIM];
__device__ float g_A   [NNODE * NHEADS];
__device__ float g_B   [NNODE * NHEADS];
__device__ float g_EA  [NNODE * NHEADS];
__device__ float g_EA5 [NNODE * NHEADS];
__device__ float g_EB  [NNODE * NHEADS];
__device__ float g_EB5 [NNODE * NHEADS];
__device__ float g_srow[NNODE * NHEADS];
__device__ float g_tmp [NNODE * DIM];
__device__ float g_x1  [NNODE * DIM];
__device__ float4 g_Wf [2 * 16 * 16 * 32];

// ---- packed f32x2 helpers ---------------------------------------------------
__device__ __forceinline__ ull pk2(float x, float y) {
    ull r; asm("mov.b64 %0, {%1, %2};" : "=l"(r) : "f"(x), "f"(y)); return r;
}
__device__ __forceinline__ float2 upk2(ull v) {
    float2 r; asm("mov.b64 {%0, %1}, %2;" : "=f"(r.x), "=f"(r.y) : "l"(v)); return r;
}
__device__ __forceinline__ void fma2(ull& d, ull a, ull b) {
    asm("fma.rn.f32x2 %0, %1, %2, %0;" : "+l"(d) : "l"(a), "l"(b));
}

// ---- tf32 helpers -------------------------------------------------------------
__device__ __forceinline__ uint cvt_tf32(float f) {
    uint r; asm("cvt.rna.tf32.f32 %0, %1;" : "=r"(r) : "f"(f)); return r;
}
__device__ __forceinline__ void mma_tf32(float& d0, float& d1, float& d2, float& d3,
                                         uint a0, uint a1, uint a2, uint a3,
                                         uint b0, uint b1) {
    asm("mma.sync.aligned.m16n8k8.row.col.f32.tf32.tf32.f32 "
        "{%0,%1,%2,%3}, {%4,%5,%6,%7}, {%8,%9}, {%0,%1,%2,%3};"
        : "+f"(d0), "+f"(d1), "+f"(d2), "+f"(d3)
        : "r"(a0), "r"(a1), "r"(a2), "r"(a3), "r"(b0), "r"(b1));
}

// ---------------------------------------------------------------------------
// K0: pack W1/W2 into fragment order with tf32 hi/lo split. (R10, unchanged)
// ---------------------------------------------------------------------------
__global__ void __launch_bounds__(256)
k_prep(const float* __restrict__ W1, const float* __restrict__ W2)
{
    const int gid   = blockIdx.x * 256 + threadIdx.x;
    const int layer = gid >> 13;
    const int e     = gid & 8191;
    const int lane  = e & 31;
    const int nt    = (e >> 5) & 15;
    const int ks    = e >> 9;

    const float* W = layer ? W2 : W1;
    const int k0 = ks * 8 + (lane & 3);
    const int n  = nt * 8 + (lane >> 2);

    const float b0 = W[k0 * 128 + n];
    const float b1 = W[(k0 + 4) * 128 + n];
    const uint b0h = cvt_tf32(b0);
    const uint b1h = cvt_tf32(b1);
    const uint b0l = cvt_tf32(b0 - __uint_as_float(b0h));
    const uint b1l = cvt_tf32(b1 - __uint_as_float(b1h));

    g_Wf[layer * 8192 + e] = make_float4(__uint_as_float(b0h), __uint_as_float(b1h),
                                         __uint_as_float(b0l), __uint_as_float(b1l));
}

// ---------------------------------------------------------------------------
// K1: h = x @ W via tensor cores (3xTF32) + attention dots + 4 exps.
// R10 layout, ONE change: x staged as hi/lo tf32 arrays -> mainloop A path is
// pure LDS -> MMA (no cvt/sub chains in the loop).
// ---------------------------------------------------------------------------
__global__ void __launch_bounds__(128)
k_gemm_attn(const float* __restrict__ x,
            const float4* __restrict__ Wf,
            const float* __restrict__ att_src,
            const float* __restrict__ att_dst)
{
    __shared__ __align__(16) float xh[16 * 132];
    __shared__ __align__(16) float xl[16 * 132];

    const int tid  = threadIdx.x;
    const int row0 = blockIdx.x * 16;

#pragma unroll
    for (int i = 0; i < 4; i++) {
        const int idx = tid + 128 * i;
        const int row = idx >> 5, c4 = idx & 31;
        const float4 v = ((const float4*)(x + row0 * 128))[idx];
        const uint hx = cvt_tf32(v.x), hy = cvt_tf32(v.y);
        const uint hz = cvt_tf32(v.z), hw = cvt_tf32(v.w);
        float4 hi, lo;
        hi.x = __uint_as_float(hx); lo.x = __uint_as_float(cvt_tf32(v.x - hi.x));
        hi.y = __uint_as_float(hy); lo.y = __uint_as_float(cvt_tf32(v.y - hi.y));
        hi.z = __uint_as_float(hz); lo.z = __uint_as_float(cvt_tf32(v.z - hi.z));
        hi.w = __uint_as_float(hw); lo.w = __uint_as_float(cvt_tf32(v.w - hi.w));
        *(float4*)&xh[row * 132 + c4 * 4] = hi;
        *(float4*)&xl[row * 132 + c4 * 4] = lo;
    }
    __syncthreads();

    const int warp = tid >> 5;
    const int lane = tid & 31;
    const int gid  = lane >> 2;
    const int tig  = lane & 3;

    float d[4][4];
#pragma unroll
    for (int nt = 0; nt < 4; nt++)
#pragma unroll
        for (int i = 0; i < 4; i++) d[nt][i] = 0.f;

#pragma unroll 4
    for (int ks = 0; ks < 16; ks++) {
        const int o0 = gid * 132 + ks * 8 + tig;
        const int o8 = (gid + 8) * 132 + ks * 8 + tig;
        const uint ah0 = __float_as_uint(xh[o0]);
        const uint ah1 = __float_as_uint(xh[o8]);
        const uint ah2 = __float_as_uint(xh[o0 + 4]);
        const uint ah3 = __float_as_uint(xh[o8 + 4]);
        const uint al0 = __float_as_uint(xl[o0]);
        const uint al1 = __float_as_uint(xl[o8]);
        const uint al2 = __float_as_uint(xl[o0 + 4]);
        const uint al3 = __float_as_uint(xl[o8 + 4]);

#pragma unroll
        for (int nt = 0; nt < 4; nt++) {
            const float4 bf = __ldg(&Wf[(ks * 16 + warp * 4 + nt) * 32 + lane]);
            const uint bh0 = __float_as_uint(bf.x);
            const uint bh1 = __float_as_uint(bf.y);
            const uint bl0 = __float_as_uint(bf.z);
            const uint bl1 = __float_as_uint(bf.w);
            mma_tf32(d[nt][0], d[nt][1], d[nt][2], d[nt][3],
                     ah0, ah1, ah2, ah3, bh0, bh1);
            mma_tf32(d[nt][0], d[nt][1], d[nt][2], d[nt][3],
                     ah0, ah1, ah2, ah3, bl0, bl1);
            mma_tf32(d[nt][0], d[nt][1], d[nt][2], d[nt][3],
                     al0, al1, al2, al3, bh0, bh1);
        }
    }

    float psr0 = 0.f, psr8 = 0.f, pdr0 = 0.f, pdr8 = 0.f;
#pragma unroll
    for (int nt = 0; nt < 4; nt++) {
        const int col = warp * 32 + nt * 8 + 2 * tig;
        *(float2*)&g_h[(row0 + gid) * 128 + col]     = make_float2(d[nt][0], d[nt][1]);
        *(float2*)&g_h[(row0 + gid + 8) * 128 + col] = make_float2(d[nt][2], d[nt][3]);

        const float2 as = *(const float2*)&att_src[col];
        const float2 ad = *(const float2*)&att_dst[col];
        psr0 += d[nt][0] * as.x + d[nt][1] * as.y;
        psr8 += d[nt][2] * as.x + d[nt][3] * as.y;
        pdr0 += d[nt][0] * ad.x + d[nt][1] * ad.y;
        pdr8 += d[nt][2] * ad.x + d[nt][3] * ad.y;
    }
#pragma unroll
    for (int o = 1; o < 4; o <<= 1) {
        psr0 += __shfl_xor_sync(0xffffffffu, psr0, o);
        psr8 += __shfl_xor_sync(0xffffffffu, psr8, o);
        pdr0 += __shfl_xor_sync(0xffffffffu, pdr0, o);
        pdr8 += __shfl_xor_sync(0xffffffffu, pdr8, o);
    }
    if (tig == 0) {
        const int n0 = row0 + gid;
        const int n8 = row0 + gid + 8;
        int i4 = n0 * 4 + warp;
        g_A[i4] = psr0;  g_B[i4] = pdr0;
        g_EA[i4]  = __expf(psr0);        g_EB[i4]  = __expf(pdr0);
        g_EA5[i4] = __expf(0.2f * psr0); g_EB5[i4] = __expf(0.2f * pdr0);
        i4 = n8 * 4 + warp;
        g_A[i4] = psr8;  g_B[i4] = pdr8;
        g_EA[i4]  = __expf(psr8);        g_EB[i4]  = __expf(pdr8);
        g_EA5[i4] = __expf(0.2f * psr8); g_EB5[i4] = __expf(0.2f * pdr8);
    }
}

// ---------------------------------------------------------------------------
// K2: row aggregation (unnormalized) + row part of softmax denominator.
// (R10 exact: block = (r, head, c-half), grid = 384, 128 threads)
// ---------------------------------------------------------------------------
__global__ void __launch_bounds__(128)
k_row_agg()
{
    const int b  = blockIdx.x;
    const int r  = b >> 3;
    const int hh = (b >> 1) & 3;
    const int ch = b & 1;

    __shared__ __align__(16) float Hs[128 * 36];
    __shared__ __align__(16) float ws[32 * 68];
    __shared__ float As[128], EAs[128], EA5s[128];
    __shared__ float Bs[64], EBs[64], EB5s[64];
    __shared__ float Ssum2[2][64];

    const int tid = threadIdx.x;

#pragma unroll
    for (int i = tid; i < 1024; i += 128) {
        const int cp = i >> 3, v = i & 7;
        *(float4*)&Hs[cp * 36 + v * 4] =
            *(const float4*)&g_h[(r * 128 + cp) * 128 + hh * 32 + v * 4];
    }
    {
        const int idx = (r * 128 + tid) * 4 + hh;
        As  [tid] = g_A  [idx];
        EAs [tid] = g_EA [idx];
        EA5s[tid] = g_EA5[idx];
    }
    if (tid < 64) {
        const int idx = (r * 128 + ch * 64 + tid) * 4 + hh;
        Bs  [tid] = g_B  [idx];
        EBs [tid] = g_EB [idx];
        EB5s[tid] = g_EB5[idx];
    }
    __syncthreads();

    const int d  = tid & 63;
    const int jh = tid >> 6;
    const float Bv   = Bs[d];
    const float EBv  = EBs[d];
    const float EB5v = EB5s[d];
    float srun = 0.f;

    const int dg = tid >> 3;
    const int qg = tid & 7;

    ull acc2[4][2];
#pragma unroll
    for (int a = 0; a < 4; a++) { acc2[a][0] = 0ull; acc2[a][1] = 0ull; }

    for (int cc = 0; cc < 4; cc++) {
#pragma unroll
        for (int jj = 0; jj < 16; jj++) {
            const int j  = jh * 16 + jj;
            const int jx = cc * 32 + j;
            const float xv = As[jx] + Bv;
            const float w = xv > 0.f ? EAs[jx] * EBv : EA5s[jx] * EB5v;
            ws[j * 68 + d] = w;
            srun += w;
        }
        __syncthreads();

#pragma unroll
        for (int j = 0; j < 32; j++) {
            const float4 wv = *(const float4*)&ws[j * 68 + dg * 4];
            const ulonglong2 hv = *(const ulonglong2*)&Hs[(cc * 32 + j) * 36 + qg * 4];
            ull ww;
            ww = pk2(wv.x, wv.x); fma2(acc2[0][0], ww, hv.x); fma2(acc2[0][1], ww, hv.y);
            ww = pk2(wv.y, wv.y); fma2(acc2[1][0], ww, hv.x); fma2(acc2[1][1], ww, hv.y);
            ww = pk2(wv.z, wv.z); fma2(acc2[2][0], ww, hv.x); fma2(acc2[2][1], ww, hv.y);
            ww = pk2(wv.w, wv.w); fma2(acc2[3][0], ww, hv.x); fma2(acc2[3][1], ww, hv.y);
        }
        __syncthreads();
    }

#pragma unroll
    for (int a = 0; a < 4; a++) {
        const int dst = ch * 64 + dg * 4 + a;
        const float2 lo = upk2(acc2[a][0]);
        const float2 hi = upk2(acc2[a][1]);
        *(float4*)&g_tmp[(r * 128 + dst) * 128 + hh * 32 + qg * 4] =
            make_float4(lo.x, lo.y, hi.x, hi.y);
    }

    Ssum2[jh][d] = srun;
    __syncthreads();
    if (tid < 64)
        g_srow[(r * 128 + ch * 64 + tid) * 4 + hh] = Ssum2[0][tid] + Ssum2[1][tid];
}

// ---------------------------------------------------------------------------
// K3: column aggregation + denominator finalize + normalize + bias + ELU.
// (R10 exact: block per column c, grid = 128, 384 threads)
// ---------------------------------------------------------------------------
__global__ void __launch_bounds__(384)
k_col_agg(const float* __restrict__ bias, float* __restrict__ out)
{
    const int c   = blockIdx.x;
    const int tid = threadIdx.x;

    __shared__ __align__(16) float Hs[48 * 136];
    __shared__ __align__(16) float ws[16 * 224];
    __shared__ float Acol[192], EAc[192], EA5c[192];
    __shared__ float Brc[192], EBrc[192], EB5rc[192];
    __shared__ float Srow[192], Rd[192];
    __shared__ float Sc2[2][192];
    __shared__ float bsh[128];

#pragma unroll
    for (int i = tid; i < 1536; i += 384) {
        const int t = i >> 5, v = i & 31;
        *(float4*)&Hs[t * 136 + v * 4] =
            *(const float4*)&g_h[(t * 128 + c) * 128 + v * 4];
    }
    if (tid < 192) {
        const int t = tid >> 2, h = tid & 3;
        const int idx = (t * 128 + c) * 4 + h;
        Acol [tid] = g_A   [idx];
        EAc  [tid] = g_EA  [idx];
        EA5c [tid] = g_EA5 [idx];
        Brc  [tid] = g_B   [idx];
        EBrc [tid] = g_EB  [idx];
        EB5rc[tid] = g_EB5 [idx];
        Srow [tid] = g_srow[idx];
    } else if (tid < 320) {
        bsh[tid - 192] = bias[tid - 192];
    }
    __syncthreads();

    const int k    = tid < 192 ? tid : tid - 192;
    const int half = tid < 192 ? 0 : 1;
    const int rr   = k >> 2;
    const int h    = k & 3;
    const float Bv   = Brc[k];
    const float EBv  = EBrc[k];
    const float EB5v = EB5rc[k];
    float scrun = 0.f;

    const int rg   = tid >> 5;
    const int head = (tid >> 3) & 3;
    const int qg   = tid & 7;

    ull acc2[4][2];
#pragma unroll
    for (int a = 0; a < 4; a++) { acc2[a][0] = 0ull; acc2[a][1] = 0ull; }

    for (int chunk = 0; chunk < 3; chunk++) {
        const int t0 = chunk * 16;
#pragma unroll
        for (int i = 0; i < 8; i++) {
            const int tl = half * 8 + i;
            const int t  = t0 + tl;
            const int sx = t * 4 + h;
            const float xv = Acol[sx] + Bv;
            float w = xv > 0.f ? EAc[sx] * EBv : EA5c[sx] * EB5v;
            if (t == rr) w = 0.f;
            ws[tl * 224 + h * 56 + rr] = w;
            scrun += w;
        }
        __syncthreads();

#pragma unroll
        for (int tl = 0; tl < 16; tl++) {
            const float4 wv = *(const float4*)&ws[tl * 224 + head * 56 + rg * 4];
            const ulonglong2 hv =
                *(const ulonglong2*)&Hs[(t0 + tl) * 136 + head * 32 + qg * 4];
            ull ww;
            ww = pk2(wv.x, wv.x); fma2(acc2[0][0], ww, hv.x); fma2(acc2[0][1], ww, hv.y);
            ww = pk2(wv.y, wv.y); fma2(acc2[1][0], ww, hv.x); fma2(acc2[1][1], ww, hv.y);
            ww = pk2(wv.z, wv.z); fma2(acc2[2][0], ww, hv.x); fma2(acc2[2][1], ww, hv.y);
            ww = pk2(wv.w, wv.w); fma2(acc2[3][0], ww, hv.x); fma2(acc2[3][1], ww, hv.y);
        }
        __syncthreads();
    }

    Sc2[half][k] = scrun;
    __syncthreads();
    if (tid < 192)
        Rd[tid] = 1.f / (Srow[tid] + Sc2[0][tid] + Sc2[1][tid]);
    __syncthreads();

    const int bb = head * 32 + qg * 4;
    const float4 bv = *(const float4*)&bsh[bb];
#pragma unroll
    for (int a = 0; a < 4; a++) {
        const int r = rg * 4 + a;
        const float rd = Rd[r * 4 + head];
        const int base = (r * 128 + c) * 128 + bb;
        const float4 tv = *(const float4*)&g_tmp[base];
        const float2 lo = upk2(acc2[a][0]);
        const float2 hi = upk2(acc2[a][1]);
        float v0 = (lo.x + tv.x) * rd + bv.x;
        float v1 = (lo.y + tv.y) * rd + bv.y;
        float v2 = (hi.x + tv.z) * rd + bv.z;
        float v3 = (hi.y + tv.w) * rd + bv.w;
        v0 = v0 > 0.f ? v0 : (__expf(v0) - 1.f);
        v1 = v1 > 0.f ? v1 : (__expf(v1) - 1.f);
        v2 = v2 > 0.f ? v2 : (__expf(v2) - 1.f);
        v3 = v3 > 0.f ? v3 : (__expf(v3) - 1.f);
        *(float4*)&out[base] = make_float4(v0, v1, v2, v3);
    }
}

// ---------------------------------------------------------------------------
static void run_layer(const float* x, const float4* Wf, const float* asrc,
                      const float* adst, const float* bias, float* out)
{
    k_gemm_attn<<<NNODE / 16, 128>>>(x, Wf, asrc, adst);
    k_row_agg<<<T_TRIG * NHEADS * 2, 128>>>();
    k_col_agg<<<S_SPAN, 384>>>(bias, out);
}

extern "C" void kernel_launch(void* const* d_in, const int* in_sizes, int n_in,
                              void* d_out, int out_size)
{
    const float* x0  = (const float*)d_in[0];
    const float* W1  = (const float*)d_in[1];
    const float* as1 = (const float*)d_in[2];
    const float* ad1 = (const float*)d_in[3];
    const float* b1  = (const float*)d_in[4];
    const float* W2  = (const float*)d_in[5];
    const float* as2 = (const float*)d_in[6];
    const float* ad2 = (const float*)d_in[7];
    const float* b2  = (const float*)d_in[8];

    float* x1 = nullptr;
    cudaGetSymbolAddress((void**)&x1, g_x1);
    float4* Wf = nullptr;
    cudaGetSymbolAddress((void**)&Wf, g_Wf);

    k_prep<<<64, 256>>>(W1, W2);
    run_layer(x0, Wf,        as1, ad1, b1, x1);
    run_layer(x1, Wf + 8192, as2, ad2, b2, (float*)d_out);
}